// round 1
// baseline (speedup 1.0000x reference)
#include <cuda_runtime.h>
#include <math.h>

// Problem constants
constexpr int B_  = 4;
constexpr int S_  = 2048;
constexpr int D_  = 1024;
constexpr int H_  = 16;
constexpr int DK_ = 64;
constexpr int M_  = B_ * S_;   // 8192 rows

// Scratch (device globals — no allocation allowed)
__device__ float g_q[(size_t)B_ * H_ * S_ * DK_];   // [B,H,S,DK]
__device__ float g_k[(size_t)B_ * H_ * S_ * DK_];
__device__ float g_v[(size_t)B_ * H_ * S_ * DK_];
__device__ float g_ctx[(size_t)B_ * S_ * D_];       // [B,S,D]

// ---------------------------------------------------------------------------
// Projection GEMM: Y = X @ W^T + bias, written into split-head layout.
// BM=128, BN=128, BK=8, 256 threads, 8x8 per thread.
// ---------------------------------------------------------------------------
__global__ __launch_bounds__(256, 2) void proj_kernel(
    const float* __restrict__ X, const float* __restrict__ W,
    const float* __restrict__ bias, int which)
{
    __shared__ float As[8][128];
    __shared__ float Bs[8][128];

    const int tid = threadIdx.x;
    const int m0 = blockIdx.y * 128;
    const int n0 = blockIdx.x * 128;
    const int tr = tid >> 4;        // 0..15 (row block)
    const int tc = tid & 15;        // 0..15 (col block)
    const int lrow = tid >> 1;      // 0..127
    const int lq = (tid & 1) * 4;   // 0 or 4

    float acc[8][8];
#pragma unroll
    for (int i = 0; i < 8; i++)
#pragma unroll
        for (int j = 0; j < 8; j++) acc[i][j] = 0.f;

    const float* xg = X + (size_t)(m0 + lrow) * D_ + lq;
    const float* wg = W + (size_t)(n0 + lrow) * D_ + lq;

    for (int k0 = 0; k0 < D_; k0 += 8) {
        float4 a  = *(const float4*)(xg + k0);
        float4 bb = *(const float4*)(wg + k0);
        As[lq + 0][lrow] = a.x;  As[lq + 1][lrow] = a.y;
        As[lq + 2][lrow] = a.z;  As[lq + 3][lrow] = a.w;
        Bs[lq + 0][lrow] = bb.x; Bs[lq + 1][lrow] = bb.y;
        Bs[lq + 2][lrow] = bb.z; Bs[lq + 3][lrow] = bb.w;
        __syncthreads();
#pragma unroll
        for (int kk = 0; kk < 8; kk++) {
            float4 a0 = *(const float4*)&As[kk][tr * 8];
            float4 a1 = *(const float4*)&As[kk][tr * 8 + 4];
            float4 b0 = *(const float4*)&Bs[kk][tc * 8];
            float4 b1 = *(const float4*)&Bs[kk][tc * 8 + 4];
            float av[8] = {a0.x, a0.y, a0.z, a0.w, a1.x, a1.y, a1.z, a1.w};
            float bv[8] = {b0.x, b0.y, b0.z, b0.w, b1.x, b1.y, b1.z, b1.w};
#pragma unroll
            for (int i = 0; i < 8; i++)
#pragma unroll
                for (int j = 0; j < 8; j++)
                    acc[i][j] += av[i] * bv[j];
        }
        __syncthreads();
    }

    float* out = (which == 0) ? g_q : (which == 1) ? g_k : g_v;
#pragma unroll
    for (int i = 0; i < 8; i++) {
        int mm = m0 + tr * 8 + i;
        int b = mm / S_, s = mm % S_;
#pragma unroll
        for (int j4 = 0; j4 < 8; j4 += 4) {
            int nn = n0 + tc * 8 + j4;
            int h = nn / DK_, dk = nn % DK_;  // 8-col group never crosses a head
            float4 r;
            r.x = acc[i][j4 + 0] + bias[nn + 0];
            r.y = acc[i][j4 + 1] + bias[nn + 1];
            r.z = acc[i][j4 + 2] + bias[nn + 2];
            r.w = acc[i][j4 + 3] + bias[nn + 3];
            *(float4*)&out[((size_t)(b * H_ + h) * S_ + s) * DK_ + dk] = r;
        }
    }
}

// ---------------------------------------------------------------------------
// Output projection GEMM: out = ctx @ Wo^T + bo  (plain [M,D] layout)
// ---------------------------------------------------------------------------
__global__ __launch_bounds__(256, 2) void outproj_kernel(
    const float* __restrict__ W, const float* __restrict__ bias,
    float* __restrict__ out)
{
    __shared__ float As[8][128];
    __shared__ float Bs[8][128];

    const int tid = threadIdx.x;
    const int m0 = blockIdx.y * 128;
    const int n0 = blockIdx.x * 128;
    const int tr = tid >> 4;
    const int tc = tid & 15;
    const int lrow = tid >> 1;
    const int lq = (tid & 1) * 4;

    float acc[8][8];
#pragma unroll
    for (int i = 0; i < 8; i++)
#pragma unroll
        for (int j = 0; j < 8; j++) acc[i][j] = 0.f;

    const float* xg = g_ctx + (size_t)(m0 + lrow) * D_ + lq;
    const float* wg = W + (size_t)(n0 + lrow) * D_ + lq;

    for (int k0 = 0; k0 < D_; k0 += 8) {
        float4 a  = *(const float4*)(xg + k0);
        float4 bb = *(const float4*)(wg + k0);
        As[lq + 0][lrow] = a.x;  As[lq + 1][lrow] = a.y;
        As[lq + 2][lrow] = a.z;  As[lq + 3][lrow] = a.w;
        Bs[lq + 0][lrow] = bb.x; Bs[lq + 1][lrow] = bb.y;
        Bs[lq + 2][lrow] = bb.z; Bs[lq + 3][lrow] = bb.w;
        __syncthreads();
#pragma unroll
        for (int kk = 0; kk < 8; kk++) {
            float4 a0 = *(const float4*)&As[kk][tr * 8];
            float4 a1 = *(const float4*)&As[kk][tr * 8 + 4];
            float4 b0 = *(const float4*)&Bs[kk][tc * 8];
            float4 b1 = *(const float4*)&Bs[kk][tc * 8 + 4];
            float av[8] = {a0.x, a0.y, a0.z, a0.w, a1.x, a1.y, a1.z, a1.w};
            float bv[8] = {b0.x, b0.y, b0.z, b0.w, b1.x, b1.y, b1.z, b1.w};
#pragma unroll
            for (int i = 0; i < 8; i++)
#pragma unroll
                for (int j = 0; j < 8; j++)
                    acc[i][j] += av[i] * bv[j];
        }
        __syncthreads();
    }

#pragma unroll
    for (int i = 0; i < 8; i++) {
        int mm = m0 + tr * 8 + i;
#pragma unroll
        for (int j4 = 0; j4 < 8; j4 += 4) {
            int nn = n0 + tc * 8 + j4;
            float4 r;
            r.x = acc[i][j4 + 0] + bias[nn + 0];
            r.y = acc[i][j4 + 1] + bias[nn + 1];
            r.z = acc[i][j4 + 2] + bias[nn + 2];
            r.w = acc[i][j4 + 3] + bias[nn + 3];
            *(float4*)&out[(size_t)mm * D_ + nn] = r;
        }
    }
}

// ---------------------------------------------------------------------------
// Flash attention (fp32, online softmax). One CTA = 64 queries of one (b,h).
// Thread grid 16x16: thread (x,y) owns rows {y+16*ii} and cols {x+16*jj}
// (strided ownership -> conflict-free LDS for K/V reads).
// ---------------------------------------------------------------------------
constexpr int PAD = 68;                               // row stride in floats
constexpr int SMEM_FLASH = 4 * 64 * PAD * (int)sizeof(float);  // 69632 B

__global__ __launch_bounds__(256, 2) void flash_kernel()
{
    extern __shared__ float sm[];
    float (*Qs)[PAD] = (float(*)[PAD])(sm);
    float (*Ks)[PAD] = (float(*)[PAD])(sm + 64 * PAD);
    float (*Vs)[PAD] = (float(*)[PAD])(sm + 2 * 64 * PAD);
    float (*Ps)[PAD] = (float(*)[PAD])(sm + 3 * 64 * PAD);

    const int tid = threadIdx.x;
    const int x = tid & 15;
    const int y = tid >> 4;
    const int q0 = blockIdx.x * 64;
    const int h = blockIdx.y;
    const int b = blockIdx.z;

    const size_t base = (size_t)(b * H_ + h) * S_ * DK_;
    const float* qg = g_q + base;
    const float* kg = g_k + base;
    const float* vg = g_v + base;

    const int lr = tid >> 4;          // 0..15
    const int lc = (tid & 15) * 4;    // 0..60
    const float scale = 0.125f;       // 1/sqrt(64)

    // Load Q tile once, pre-scaled
#pragma unroll
    for (int r = 0; r < 4; r++) {
        float4 t = *(const float4*)&qg[(size_t)(q0 + lr + 16 * r) * DK_ + lc];
        t.x *= scale; t.y *= scale; t.z *= scale; t.w *= scale;
        *(float4*)&Qs[lr + 16 * r][lc] = t;
    }

    float m_i[4], l_i[4], o[4][4];
#pragma unroll
    for (int i = 0; i < 4; i++) {
        m_i[i] = -1e30f;
        l_i[i] = 0.f;
#pragma unroll
        for (int j = 0; j < 4; j++) o[i][j] = 0.f;
    }

    for (int kb = 0; kb < S_; kb += 64) {
#pragma unroll
        for (int r = 0; r < 4; r++) {
            *(float4*)&Ks[lr + 16 * r][lc] =
                *(const float4*)&kg[(size_t)(kb + lr + 16 * r) * DK_ + lc];
            *(float4*)&Vs[lr + 16 * r][lc] =
                *(const float4*)&vg[(size_t)(kb + lr + 16 * r) * DK_ + lc];
        }
        __syncthreads();

        // S = Q K^T (4x4 per thread)
        float sc[4][4];
#pragma unroll
        for (int i = 0; i < 4; i++)
#pragma unroll
            for (int j = 0; j < 4; j++) sc[i][j] = 0.f;

#pragma unroll
        for (int d = 0; d < DK_; d += 4) {
            float4 qv[4], kv[4];
#pragma unroll
            for (int ii = 0; ii < 4; ii++) qv[ii] = *(const float4*)&Qs[y + 16 * ii][d];
#pragma unroll
            for (int jj = 0; jj < 4; jj++) kv[jj] = *(const float4*)&Ks[x + 16 * jj][d];
#pragma unroll
            for (int ii = 0; ii < 4; ii++)
#pragma unroll
                for (int jj = 0; jj < 4; jj++)
                    sc[ii][jj] += qv[ii].x * kv[jj].x + qv[ii].y * kv[jj].y +
                                  qv[ii].z * kv[jj].z + qv[ii].w * kv[jj].w;
        }

        // Online softmax update (row reduction across the 16 x-lanes)
#pragma unroll
        for (int ii = 0; ii < 4; ii++) {
            float mx = fmaxf(fmaxf(sc[ii][0], sc[ii][1]), fmaxf(sc[ii][2], sc[ii][3]));
#pragma unroll
            for (int off = 8; off > 0; off >>= 1)
                mx = fmaxf(mx, __shfl_xor_sync(0xffffffffu, mx, off, 16));
            float mn = fmaxf(m_i[ii], mx);
            float ssum = 0.f;
#pragma unroll
            for (int jj = 0; jj < 4; jj++) {
                float p = __expf(sc[ii][jj] - mn);
                sc[ii][jj] = p;
                ssum += p;
            }
#pragma unroll
            for (int off = 8; off > 0; off >>= 1)
                ssum += __shfl_xor_sync(0xffffffffu, ssum, off, 16);
            float alpha = __expf(m_i[ii] - mn);
            l_i[ii] = l_i[ii] * alpha + ssum;
            m_i[ii] = mn;
#pragma unroll
            for (int jj = 0; jj < 4; jj++) o[ii][jj] *= alpha;
        }

        // Stage P to smem for the PV GEMM
#pragma unroll
        for (int ii = 0; ii < 4; ii++)
#pragma unroll
            for (int jj = 0; jj < 4; jj++)
                Ps[y + 16 * ii][x + 16 * jj] = sc[ii][jj];
        __syncthreads();

        // O += P V
#pragma unroll
        for (int k4 = 0; k4 < 64; k4 += 4) {
            float4 pr[4];
#pragma unroll
            for (int ii = 0; ii < 4; ii++) pr[ii] = *(const float4*)&Ps[y + 16 * ii][k4];
            float vv0[4], vv1[4], vv2[4], vv3[4];
#pragma unroll
            for (int jj = 0; jj < 4; jj++) {
                vv0[jj] = Vs[k4 + 0][x + 16 * jj];
                vv1[jj] = Vs[k4 + 1][x + 16 * jj];
                vv2[jj] = Vs[k4 + 2][x + 16 * jj];
                vv3[jj] = Vs[k4 + 3][x + 16 * jj];
            }
#pragma unroll
            for (int ii = 0; ii < 4; ii++)
#pragma unroll
                for (int jj = 0; jj < 4; jj++)
                    o[ii][jj] += pr[ii].x * vv0[jj] + pr[ii].y * vv1[jj] +
                                 pr[ii].z * vv2[jj] + pr[ii].w * vv3[jj];
        }
        __syncthreads();
    }

    // Normalize + write ctx in [B,S,D] layout
#pragma unroll
    for (int ii = 0; ii < 4; ii++) {
        float inv = 1.0f / l_i[ii];
        int s = q0 + y + 16 * ii;
        size_t rowbase = ((size_t)b * S_ + s) * D_ + h * DK_;
#pragma unroll
        for (int jj = 0; jj < 4; jj++)
            g_ctx[rowbase + x + 16 * jj] = o[ii][jj] * inv;
    }
}

// ---------------------------------------------------------------------------
// Launch
// ---------------------------------------------------------------------------
extern "C" void kernel_launch(void* const* d_in, const int* in_sizes, int n_in,
                              void* d_out, int out_size)
{
    const float* Q  = (const float*)d_in[0];
    const float* K  = (const float*)d_in[1];
    const float* V  = (const float*)d_in[2];
    const float* Wq = (const float*)d_in[3];
    const float* bq = (const float*)d_in[4];
    const float* Wk = (const float*)d_in[5];
    const float* bk = (const float*)d_in[6];
    const float* Wv = (const float*)d_in[7];
    const float* bv = (const float*)d_in[8];
    const float* Wo = (const float*)d_in[9];
    const float* bo = (const float*)d_in[10];
    float* out = (float*)d_out;

    cudaFuncSetAttribute(flash_kernel,
                         cudaFuncAttributeMaxDynamicSharedMemorySize, SMEM_FLASH);

    dim3 pgrid(D_ / 128, M_ / 128);  // (8, 64)
    proj_kernel<<<pgrid, 256>>>(Q, Wq, bq, 0);
    proj_kernel<<<pgrid, 256>>>(K, Wk, bk, 1);
    proj_kernel<<<pgrid, 256>>>(V, Wv, bv, 2);

    flash_kernel<<<dim3(S_ / 64, H_, B_), 256, SMEM_FLASH>>>();

    outproj_kernel<<<pgrid, 256>>>(Wo, bo, out);
}

// round 4
// speedup vs baseline: 1.4956x; 1.4956x over previous
#include <cuda_runtime.h>
#include <cstdint>
#include <math.h>

// Problem constants
constexpr int B_  = 4;
constexpr int S_  = 2048;
constexpr int D_  = 1024;
constexpr int H_  = 16;
constexpr int DK_ = 64;
constexpr int M_  = B_ * S_;   // 8192

// Scratch (device globals — no allocation allowed)
__device__ float g_q[(size_t)B_ * H_ * S_ * DK_];   // [B,H,S,DK]
__device__ float g_k[(size_t)B_ * H_ * S_ * DK_];
__device__ float g_v[(size_t)B_ * H_ * S_ * DK_];
__device__ float g_ctx[(size_t)B_ * S_ * D_];       // [B,S,D]

// ---------------------------------------------------------------------------
// tf32 helpers (non-suffixed PTX: works under generic sm_103 target)
// ---------------------------------------------------------------------------
__device__ __forceinline__ uint32_t f2tf32(float f) {
    uint32_t r;
    asm("cvt.rna.tf32.f32 %0, %1;" : "=r"(r) : "f"(f));
    return r;
}

__device__ __forceinline__ void mma_tf32_16n8k8(float* c, const uint32_t* a,
                                                const uint32_t* b) {
    asm volatile(
        "mma.sync.aligned.m16n8k8.row.col.f32.tf32.tf32.f32 "
        "{%0,%1,%2,%3}, {%4,%5,%6,%7}, {%8,%9}, {%0,%1,%2,%3};"
        : "+f"(c[0]), "+f"(c[1]), "+f"(c[2]), "+f"(c[3])
        : "r"(a[0]), "r"(a[1]), "r"(a[2]), "r"(a[3]), "r"(b[0]), "r"(b[1]));
}

// ---------------------------------------------------------------------------
// TF32 tensor-core GEMM: Y[M,N] = X @ W^T + bias
// BM=BN=128, BK=16, 256 threads, 8 warps (4x2), warp tile 32x64.
// which: 0/1/2 -> g_q/g_k/g_v split-head [B,H,S,DK]; 3 -> read g_ctx (device
// symbol, resolved DEVICE-SIDE), write dst [M,D] plain.
// ---------------------------------------------------------------------------
constexpr int BK  = 16;
constexpr int LDA = 20;   // padded row stride (floats)

__global__ __launch_bounds__(256, 2) void gemm_tf32(
    const float* __restrict__ X, const float* __restrict__ W,
    const float* __restrict__ bias, float* __restrict__ dst, int which)
{
    __shared__ uint32_t As[2][128 * LDA];
    __shared__ uint32_t Bs[2][128 * LDA];

    const int tid = threadIdx.x;
    const int wid = tid >> 5;
    const int lane = tid & 31;
    const int m0 = blockIdx.y * 128;
    const int n0 = blockIdx.x * 128;
    const int warp_m = (wid & 3) * 32;
    const int warp_n = (wid >> 2) * 64;

    // FIX (R3 bug): device-global input must be resolved in device code.
    // Passing g_ctx as a host-side kernel arg took the HOST shadow address,
    // which GB300's ATS happily dereferenced (host BSS zeros) -> output 0.
    const float* Xin = (which == 3) ? (const float*)g_ctx : X;

    // Tile-load mapping: thread handles rows r0 and r0+64, 4 k-elems at kq.
    const int r0 = tid >> 2;
    const int kq = (tid & 3) * 4;

    const float* gA = Xin + (size_t)m0 * D_;
    const float* gB = W + (size_t)n0 * D_;

    float acc[2][8][4];
#pragma unroll
    for (int i = 0; i < 2; i++)
#pragma unroll
        for (int j = 0; j < 8; j++)
#pragma unroll
            for (int r = 0; r < 4; r++) acc[i][j][r] = 0.f;

    float4 pa0, pa1, pb0, pb1;

    auto ldg = [&](int t) {
        const float* a = gA + (size_t)r0 * D_ + t * BK + kq;
        pa0 = *(const float4*)a;
        pa1 = *(const float4*)(a + (size_t)64 * D_);
        const float* b = gB + (size_t)r0 * D_ + t * BK + kq;
        pb0 = *(const float4*)b;
        pb1 = *(const float4*)(b + (size_t)64 * D_);
    };
    auto sts = [&](int s) {
        uint32_t* A = As[s];
        uint32_t* Bsh = Bs[s];
        int o0 = r0 * LDA + kq;
        int o1 = (r0 + 64) * LDA + kq;
        A[o0 + 0] = f2tf32(pa0.x); A[o0 + 1] = f2tf32(pa0.y);
        A[o0 + 2] = f2tf32(pa0.z); A[o0 + 3] = f2tf32(pa0.w);
        A[o1 + 0] = f2tf32(pa1.x); A[o1 + 1] = f2tf32(pa1.y);
        A[o1 + 2] = f2tf32(pa1.z); A[o1 + 3] = f2tf32(pa1.w);
        Bsh[o0 + 0] = f2tf32(pb0.x); Bsh[o0 + 1] = f2tf32(pb0.y);
        Bsh[o0 + 2] = f2tf32(pb0.z); Bsh[o0 + 3] = f2tf32(pb0.w);
        Bsh[o1 + 0] = f2tf32(pb1.x); Bsh[o1 + 1] = f2tf32(pb1.y);
        Bsh[o1 + 2] = f2tf32(pb1.z); Bsh[o1 + 3] = f2tf32(pb1.w);
    };

    ldg(0);
    sts(0);
    __syncthreads();

    const int r8 = lane >> 2;
    const int c4 = lane & 3;

    for (int t = 0; t < D_ / BK; t++) {
        int s = t & 1;
        if (t < D_ / BK - 1) ldg(t + 1);

#pragma unroll
        for (int ks = 0; ks < 2; ks++) {
            const int kk = ks * 8;
            uint32_t a[2][4], b[8][2];
#pragma unroll
            for (int im = 0; im < 2; im++) {
                int mr = warp_m + 16 * im + r8;
                a[im][0] = As[s][mr * LDA + kk + c4];
                a[im][1] = As[s][(mr + 8) * LDA + kk + c4];
                a[im][2] = As[s][mr * LDA + kk + c4 + 4];
                a[im][3] = As[s][(mr + 8) * LDA + kk + c4 + 4];
            }
#pragma unroll
            for (int jn = 0; jn < 8; jn++) {
                int nr = warp_n + 8 * jn + r8;
                b[jn][0] = Bs[s][nr * LDA + kk + c4];
                b[jn][1] = Bs[s][nr * LDA + kk + c4 + 4];
            }
#pragma unroll
            for (int im = 0; im < 2; im++)
#pragma unroll
                for (int jn = 0; jn < 8; jn++)
                    mma_tf32_16n8k8(acc[im][jn], a[im], b[jn]);
        }

        if (t < D_ / BK - 1) sts(s ^ 1);
        __syncthreads();
    }

    // Epilogue: direct global stores (float2) with bias.
    float* sh_out = (which == 0) ? g_q : (which == 1) ? g_k
                  : (which == 2) ? g_v : dst;
    const int c2 = (lane & 3) * 2;
#pragma unroll
    for (int im = 0; im < 2; im++) {
#pragma unroll
        for (int jn = 0; jn < 8; jn++) {
            int n = n0 + warp_n + 8 * jn + c2;
            float bx = bias[n], by = bias[n + 1];
            int mA = m0 + warp_m + 16 * im + r8;
            int mB = mA + 8;
            float2 v0 = make_float2(acc[im][jn][0] + bx, acc[im][jn][1] + by);
            float2 v1 = make_float2(acc[im][jn][2] + bx, acc[im][jn][3] + by);
            if (which < 3) {
                int h = n >> 6, dk = n & 63;
                int bA = mA >> 11, sA = mA & (S_ - 1);
                int bB = mB >> 11, sB = mB & (S_ - 1);
                *(float2*)&sh_out[(((size_t)(bA * H_ + h) * S_ + sA) << 6) + dk] = v0;
                *(float2*)&sh_out[(((size_t)(bB * H_ + h) * S_ + sB) << 6) + dk] = v1;
            } else {
                *(float2*)&sh_out[(size_t)mA * D_ + n] = v0;
                *(float2*)&sh_out[(size_t)mB * D_ + n] = v1;
            }
        }
    }
}

// ---------------------------------------------------------------------------
// Flash attention (fp32, online softmax) — unchanged from R1 (proven).
// ---------------------------------------------------------------------------
constexpr int PAD = 68;
constexpr int SMEM_FLASH = 4 * 64 * PAD * (int)sizeof(float);

__global__ __launch_bounds__(256, 2) void flash_kernel()
{
    extern __shared__ float sm[];
    float (*Qs)[PAD] = (float(*)[PAD])(sm);
    float (*Ks)[PAD] = (float(*)[PAD])(sm + 64 * PAD);
    float (*Vs)[PAD] = (float(*)[PAD])(sm + 2 * 64 * PAD);
    float (*Ps)[PAD] = (float(*)[PAD])(sm + 3 * 64 * PAD);

    const int tid = threadIdx.x;
    const int x = tid & 15;
    const int y = tid >> 4;
    const int q0 = blockIdx.x * 64;
    const int h = blockIdx.y;
    const int b = blockIdx.z;

    const size_t base = (size_t)(b * H_ + h) * S_ * DK_;
    const float* qg = g_q + base;
    const float* kg = g_k + base;
    const float* vg = g_v + base;

    const int lr = tid >> 4;
    const int lc = (tid & 15) * 4;
    const float scale = 0.125f;

#pragma unroll
    for (int r = 0; r < 4; r++) {
        float4 t = *(const float4*)&qg[(size_t)(q0 + lr + 16 * r) * DK_ + lc];
        t.x *= scale; t.y *= scale; t.z *= scale; t.w *= scale;
        *(float4*)&Qs[lr + 16 * r][lc] = t;
    }

    float m_i[4], l_i[4], o[4][4];
#pragma unroll
    for (int i = 0; i < 4; i++) {
        m_i[i] = -1e30f;
        l_i[i] = 0.f;
#pragma unroll
        for (int j = 0; j < 4; j++) o[i][j] = 0.f;
    }

    for (int kb = 0; kb < S_; kb += 64) {
#pragma unroll
        for (int r = 0; r < 4; r++) {
            *(float4*)&Ks[lr + 16 * r][lc] =
                *(const float4*)&kg[(size_t)(kb + lr + 16 * r) * DK_ + lc];
            *(float4*)&Vs[lr + 16 * r][lc] =
                *(const float4*)&vg[(size_t)(kb + lr + 16 * r) * DK_ + lc];
        }
        __syncthreads();

        float sc[4][4];
#pragma unroll
        for (int i = 0; i < 4; i++)
#pragma unroll
            for (int j = 0; j < 4; j++) sc[i][j] = 0.f;

#pragma unroll
        for (int d = 0; d < DK_; d += 4) {
            float4 qv[4], kv[4];
#pragma unroll
            for (int ii = 0; ii < 4; ii++) qv[ii] = *(const float4*)&Qs[y + 16 * ii][d];
#pragma unroll
            for (int jj = 0; jj < 4; jj++) kv[jj] = *(const float4*)&Ks[x + 16 * jj][d];
#pragma unroll
            for (int ii = 0; ii < 4; ii++)
#pragma unroll
                for (int jj = 0; jj < 4; jj++)
                    sc[ii][jj] += qv[ii].x * kv[jj].x + qv[ii].y * kv[jj].y +
                                  qv[ii].z * kv[jj].z + qv[ii].w * kv[jj].w;
        }

#pragma unroll
        for (int ii = 0; ii < 4; ii++) {
            float mx = fmaxf(fmaxf(sc[ii][0], sc[ii][1]), fmaxf(sc[ii][2], sc[ii][3]));
#pragma unroll
            for (int off = 8; off > 0; off >>= 1)
                mx = fmaxf(mx, __shfl_xor_sync(0xffffffffu, mx, off, 16));
            float mn = fmaxf(m_i[ii], mx);
            float ssum = 0.f;
#pragma unroll
            for (int jj = 0; jj < 4; jj++) {
                float p = __expf(sc[ii][jj] - mn);
                sc[ii][jj] = p;
                ssum += p;
            }
#pragma unroll
            for (int off = 8; off > 0; off >>= 1)
                ssum += __shfl_xor_sync(0xffffffffu, ssum, off, 16);
            float alpha = __expf(m_i[ii] - mn);
            l_i[ii] = l_i[ii] * alpha + ssum;
            m_i[ii] = mn;
#pragma unroll
            for (int jj = 0; jj < 4; jj++) o[ii][jj] *= alpha;
        }

#pragma unroll
        for (int ii = 0; ii < 4; ii++)
#pragma unroll
            for (int jj = 0; jj < 4; jj++)
                Ps[y + 16 * ii][x + 16 * jj] = sc[ii][jj];
        __syncthreads();

#pragma unroll
        for (int k4 = 0; k4 < 64; k4 += 4) {
            float4 pr[4];
#pragma unroll
            for (int ii = 0; ii < 4; ii++) pr[ii] = *(const float4*)&Ps[y + 16 * ii][k4];
            float vv0[4], vv1[4], vv2[4], vv3[4];
#pragma unroll
            for (int jj = 0; jj < 4; jj++) {
                vv0[jj] = Vs[k4 + 0][x + 16 * jj];
                vv1[jj] = Vs[k4 + 1][x + 16 * jj];
                vv2[jj] = Vs[k4 + 2][x + 16 * jj];
                vv3[jj] = Vs[k4 + 3][x + 16 * jj];
            }
#pragma unroll
            for (int ii = 0; ii < 4; ii++)
#pragma unroll
                for (int jj = 0; jj < 4; jj++)
                    o[ii][jj] += pr[ii].x * vv0[jj] + pr[ii].y * vv1[jj] +
                                 pr[ii].z * vv2[jj] + pr[ii].w * vv3[jj];
        }
        __syncthreads();
    }

#pragma unroll
    for (int ii = 0; ii < 4; ii++) {
        float inv = 1.0f / l_i[ii];
        int s = q0 + y + 16 * ii;
        size_t rowbase = ((size_t)b * S_ + s) * D_ + h * DK_;
#pragma unroll
        for (int jj = 0; jj < 4; jj++)
            g_ctx[rowbase + x + 16 * jj] = o[ii][jj] * inv;
    }
}

// ---------------------------------------------------------------------------
// Launch
// ---------------------------------------------------------------------------
extern "C" void kernel_launch(void* const* d_in, const int* in_sizes, int n_in,
                              void* d_out, int out_size)
{
    const float* Q  = (const float*)d_in[0];
    const float* K  = (const float*)d_in[1];
    const float* V  = (const float*)d_in[2];
    const float* Wq = (const float*)d_in[3];
    const float* bq = (const float*)d_in[4];
    const float* Wk = (const float*)d_in[5];
    const float* bk = (const float*)d_in[6];
    const float* Wv = (const float*)d_in[7];
    const float* bv = (const float*)d_in[8];
    const float* Wo = (const float*)d_in[9];
    const float* bo = (const float*)d_in[10];
    float* out = (float*)d_out;

    cudaFuncSetAttribute(flash_kernel,
                         cudaFuncAttributeMaxDynamicSharedMemorySize, SMEM_FLASH);

    dim3 ggrid(D_ / 128, M_ / 128);   // (8, 64)
    gemm_tf32<<<ggrid, 256>>>(Q, Wq, bq, nullptr, 0);
    gemm_tf32<<<ggrid, 256>>>(K, Wk, bk, nullptr, 1);
    gemm_tf32<<<ggrid, 256>>>(V, Wv, bv, nullptr, 2);

    flash_kernel<<<dim3(S_ / 64, H_, B_), 256, SMEM_FLASH>>>();

    gemm_tf32<<<ggrid, 256>>>(nullptr, Wo, bo, out, 3);  // input = g_ctx (device-side)
}

// round 5
// speedup vs baseline: 2.9909x; 1.9997x over previous
#include <cuda_runtime.h>
#include <cstdint>
#include <math.h>

// Problem constants
constexpr int B_  = 4;
constexpr int S_  = 2048;
constexpr int D_  = 1024;
constexpr int H_  = 16;
constexpr int DK_ = 64;
constexpr int M_  = B_ * S_;   // 8192

// Scratch (device globals — no allocation allowed)
__device__ float g_q[(size_t)B_ * H_ * S_ * DK_];   // [B,H,S,DK]
__device__ float g_k[(size_t)B_ * H_ * S_ * DK_];
__device__ float g_v[(size_t)B_ * H_ * S_ * DK_];
__device__ float g_ctx[(size_t)B_ * S_ * D_];       // [B,S,D]

// ---------------------------------------------------------------------------
// tf32 helpers (non-suffixed PTX: works under generic sm_103 target)
// ---------------------------------------------------------------------------
__device__ __forceinline__ uint32_t f2tf32(float f) {
    uint32_t r;
    asm("cvt.rna.tf32.f32 %0, %1;" : "=r"(r) : "f"(f));
    return r;
}

__device__ __forceinline__ void mma_tf32_16n8k8(float* c, const uint32_t* a,
                                                uint32_t b0, uint32_t b1) {
    asm volatile(
        "mma.sync.aligned.m16n8k8.row.col.f32.tf32.tf32.f32 "
        "{%0,%1,%2,%3}, {%4,%5,%6,%7}, {%8,%9}, {%0,%1,%2,%3};"
        : "+f"(c[0]), "+f"(c[1]), "+f"(c[2]), "+f"(c[3])
        : "r"(a[0]), "r"(a[1]), "r"(a[2]), "r"(a[3]), "r"(b0), "r"(b1));
}

// ---------------------------------------------------------------------------
// TF32 tensor-core GEMM: Y[M,N] = X @ W^T + bias  (unchanged from R4, proven)
// ---------------------------------------------------------------------------
constexpr int BK  = 16;
constexpr int LDA = 20;

__global__ __launch_bounds__(256, 2) void gemm_tf32(
    const float* __restrict__ X, const float* __restrict__ W,
    const float* __restrict__ bias, float* __restrict__ dst, int which)
{
    __shared__ uint32_t As[2][128 * LDA];
    __shared__ uint32_t Bs[2][128 * LDA];

    const int tid = threadIdx.x;
    const int wid = tid >> 5;
    const int lane = tid & 31;
    const int m0 = blockIdx.y * 128;
    const int n0 = blockIdx.x * 128;
    const int warp_m = (wid & 3) * 32;
    const int warp_n = (wid >> 2) * 64;

    const float* Xin = (which == 3) ? (const float*)g_ctx : X;

    const int r0 = tid >> 2;
    const int kq = (tid & 3) * 4;

    const float* gA = Xin + (size_t)m0 * D_;
    const float* gB = W + (size_t)n0 * D_;

    float acc[2][8][4];
#pragma unroll
    for (int i = 0; i < 2; i++)
#pragma unroll
        for (int j = 0; j < 8; j++)
#pragma unroll
            for (int r = 0; r < 4; r++) acc[i][j][r] = 0.f;

    float4 pa0, pa1, pb0, pb1;

    auto ldg = [&](int t) {
        const float* a = gA + (size_t)r0 * D_ + t * BK + kq;
        pa0 = *(const float4*)a;
        pa1 = *(const float4*)(a + (size_t)64 * D_);
        const float* b = gB + (size_t)r0 * D_ + t * BK + kq;
        pb0 = *(const float4*)b;
        pb1 = *(const float4*)(b + (size_t)64 * D_);
    };
    auto sts = [&](int s) {
        uint32_t* A = As[s];
        uint32_t* Bsh = Bs[s];
        int o0 = r0 * LDA + kq;
        int o1 = (r0 + 64) * LDA + kq;
        A[o0 + 0] = f2tf32(pa0.x); A[o0 + 1] = f2tf32(pa0.y);
        A[o0 + 2] = f2tf32(pa0.z); A[o0 + 3] = f2tf32(pa0.w);
        A[o1 + 0] = f2tf32(pa1.x); A[o1 + 1] = f2tf32(pa1.y);
        A[o1 + 2] = f2tf32(pa1.z); A[o1 + 3] = f2tf32(pa1.w);
        Bsh[o0 + 0] = f2tf32(pb0.x); Bsh[o0 + 1] = f2tf32(pb0.y);
        Bsh[o0 + 2] = f2tf32(pb0.z); Bsh[o0 + 3] = f2tf32(pb0.w);
        Bsh[o1 + 0] = f2tf32(pb1.x); Bsh[o1 + 1] = f2tf32(pb1.y);
        Bsh[o1 + 2] = f2tf32(pb1.z); Bsh[o1 + 3] = f2tf32(pb1.w);
    };

    ldg(0);
    sts(0);
    __syncthreads();

    const int r8 = lane >> 2;
    const int c4 = lane & 3;

    for (int t = 0; t < D_ / BK; t++) {
        int s = t & 1;
        if (t < D_ / BK - 1) ldg(t + 1);

#pragma unroll
        for (int ks = 0; ks < 2; ks++) {
            const int kk = ks * 8;
            uint32_t a[2][4], b[8][2];
#pragma unroll
            for (int im = 0; im < 2; im++) {
                int mr = warp_m + 16 * im + r8;
                a[im][0] = As[s][mr * LDA + kk + c4];
                a[im][1] = As[s][(mr + 8) * LDA + kk + c4];
                a[im][2] = As[s][mr * LDA + kk + c4 + 4];
                a[im][3] = As[s][(mr + 8) * LDA + kk + c4 + 4];
            }
#pragma unroll
            for (int jn = 0; jn < 8; jn++) {
                int nr = warp_n + 8 * jn + r8;
                b[jn][0] = Bs[s][nr * LDA + kk + c4];
                b[jn][1] = Bs[s][nr * LDA + kk + c4 + 4];
            }
#pragma unroll
            for (int im = 0; im < 2; im++)
#pragma unroll
                for (int jn = 0; jn < 8; jn++)
                    mma_tf32_16n8k8(acc[im][jn], a[im], b[jn][0], b[jn][1]);
        }

        if (t < D_ / BK - 1) sts(s ^ 1);
        __syncthreads();
    }

    float* sh_out = (which == 0) ? g_q : (which == 1) ? g_k
                  : (which == 2) ? g_v : dst;
    const int c2 = (lane & 3) * 2;
#pragma unroll
    for (int im = 0; im < 2; im++) {
#pragma unroll
        for (int jn = 0; jn < 8; jn++) {
            int n = n0 + warp_n + 8 * jn + c2;
            float bx = bias[n], by = bias[n + 1];
            int mA = m0 + warp_m + 16 * im + r8;
            int mB = mA + 8;
            float2 v0 = make_float2(acc[im][jn][0] + bx, acc[im][jn][1] + by);
            float2 v1 = make_float2(acc[im][jn][2] + bx, acc[im][jn][3] + by);
            if (which < 3) {
                int h = n >> 6, dk = n & 63;
                int bA = mA >> 11, sA = mA & (S_ - 1);
                int bB = mB >> 11, sB = mB & (S_ - 1);
                *(float2*)&sh_out[(((size_t)(bA * H_ + h) * S_ + sA) << 6) + dk] = v0;
                *(float2*)&sh_out[(((size_t)(bB * H_ + h) * S_ + sB) << 6) + dk] = v1;
            } else {
                *(float2*)&sh_out[(size_t)mA * D_ + n] = v0;
                *(float2*)&sh_out[(size_t)mB * D_ + n] = v1;
            }
        }
    }
}

// ---------------------------------------------------------------------------
// Flash attention with tf32 mma.sync (NEW).
// BQ=128 q rows / CTA, KV chunks of 64, 8 warps (warp w: q rows [16w,16w+16)).
// Q held as A-fragments in registers for the whole CTA lifetime.
// K smem [key][dk]; V smem transposed [dk][key]; P per-warp smem strip.
// ---------------------------------------------------------------------------
constexpr int LDK = 68;   // K row stride (u32)
constexpr int LDV = 67;   // V^T row stride (odd -> fewer STS conflicts)
constexpr int LDP = 72;   // P row stride
constexpr int FSMEM = (64 * LDK + 64 * LDV + 128 * LDP) * 4;  // 71424 B

__global__ __launch_bounds__(256, 2) void flash_tf32()
{
    extern __shared__ uint32_t sm[];
    uint32_t* sK = sm;
    uint32_t* sV = sm + 64 * LDK;
    uint32_t* sP = sm + 64 * LDK + 64 * LDV;

    const int tid = threadIdx.x;
    const int wid = tid >> 5;
    const int lane = tid & 31;
    const int r8 = lane >> 2;
    const int c4 = lane & 3;

    const int q0 = blockIdx.x * 128;
    const int h = blockIdx.y;
    const int b = blockIdx.z;
    const size_t base = (size_t)(b * H_ + h) * S_ * DK_;
    const float* qg = g_q + base;
    const float* kg = g_k + base;
    const float* vg = g_v + base;

    // Q A-fragments (pre-scaled by 1/sqrt(DK)), loaded once.
    const int qr0 = q0 + wid * 16 + r8;
    const int qr1 = qr0 + 8;
    uint32_t aq[8][4];
#pragma unroll
    for (int kk = 0; kk < 8; kk++) {
        int d0 = kk * 8 + c4;
        aq[kk][0] = f2tf32(qg[(size_t)qr0 * DK_ + d0] * 0.125f);
        aq[kk][1] = f2tf32(qg[(size_t)qr1 * DK_ + d0] * 0.125f);
        aq[kk][2] = f2tf32(qg[(size_t)qr0 * DK_ + d0 + 4] * 0.125f);
        aq[kk][3] = f2tf32(qg[(size_t)qr1 * DK_ + d0 + 4] * 0.125f);
    }

    float m0r = -1e30f, m1r = -1e30f, l0 = 0.f, l1 = 0.f;
    float o[8][4];
#pragma unroll
    for (int j = 0; j < 8; j++)
#pragma unroll
        for (int r = 0; r < 4; r++) o[j][r] = 0.f;

    const int prow0 = wid * 16 + r8;

    for (int kb = 0; kb < S_; kb += 64) {
        __syncthreads();   // previous chunk fully consumed sK/sV
#pragma unroll
        for (int i = 0; i < 4; i++) {
            int idx = tid + i * 256;          // 0..1023
            int row = idx >> 4;               // key 0..63
            int cc = (idx & 15) * 4;          // dk
            float4 kv4 = *(const float4*)&kg[(size_t)(kb + row) * DK_ + cc];
            sK[row * LDK + cc + 0] = f2tf32(kv4.x);
            sK[row * LDK + cc + 1] = f2tf32(kv4.y);
            sK[row * LDK + cc + 2] = f2tf32(kv4.z);
            sK[row * LDK + cc + 3] = f2tf32(kv4.w);
            float4 vv4 = *(const float4*)&vg[(size_t)(kb + row) * DK_ + cc];
            sV[(cc + 0) * LDV + row] = f2tf32(vv4.x);
            sV[(cc + 1) * LDV + row] = f2tf32(vv4.y);
            sV[(cc + 2) * LDV + row] = f2tf32(vv4.z);
            sV[(cc + 3) * LDV + row] = f2tf32(vv4.w);
        }
        __syncthreads();

        // ---- S = Q K^T (per warp: 16 q x 64 keys) ----
        float s[8][4];
#pragma unroll
        for (int j = 0; j < 8; j++)
#pragma unroll
            for (int r = 0; r < 4; r++) s[j][r] = 0.f;

#pragma unroll
        for (int kk = 0; kk < 8; kk++) {
#pragma unroll
            for (int jn = 0; jn < 8; jn++) {
                uint32_t b0 = sK[(8 * jn + r8) * LDK + kk * 8 + c4];
                uint32_t b1 = sK[(8 * jn + r8) * LDK + kk * 8 + c4 + 4];
                mma_tf32_16n8k8(s[jn], aq[kk], b0, b1);
            }
        }

        // ---- online softmax (rows r8 and r8+8, quad-lane reduction) ----
        float mx0 = -1e30f, mx1 = -1e30f;
#pragma unroll
        for (int jn = 0; jn < 8; jn++) {
            mx0 = fmaxf(mx0, fmaxf(s[jn][0], s[jn][1]));
            mx1 = fmaxf(mx1, fmaxf(s[jn][2], s[jn][3]));
        }
        mx0 = fmaxf(mx0, __shfl_xor_sync(0xffffffffu, mx0, 1));
        mx0 = fmaxf(mx0, __shfl_xor_sync(0xffffffffu, mx0, 2));
        mx1 = fmaxf(mx1, __shfl_xor_sync(0xffffffffu, mx1, 1));
        mx1 = fmaxf(mx1, __shfl_xor_sync(0xffffffffu, mx1, 2));
        float mn0 = fmaxf(m0r, mx0), mn1 = fmaxf(m1r, mx1);
        float alpha0 = __expf(m0r - mn0), alpha1 = __expf(m1r - mn1);
        float sum0 = 0.f, sum1 = 0.f;
#pragma unroll
        for (int jn = 0; jn < 8; jn++) {
            s[jn][0] = __expf(s[jn][0] - mn0);
            s[jn][1] = __expf(s[jn][1] - mn0);
            s[jn][2] = __expf(s[jn][2] - mn1);
            s[jn][3] = __expf(s[jn][3] - mn1);
            sum0 += s[jn][0] + s[jn][1];
            sum1 += s[jn][2] + s[jn][3];
        }
        sum0 += __shfl_xor_sync(0xffffffffu, sum0, 1);
        sum0 += __shfl_xor_sync(0xffffffffu, sum0, 2);
        sum1 += __shfl_xor_sync(0xffffffffu, sum1, 1);
        sum1 += __shfl_xor_sync(0xffffffffu, sum1, 2);
        l0 = l0 * alpha0 + sum0;
        l1 = l1 * alpha1 + sum1;
        m0r = mn0;
        m1r = mn1;
#pragma unroll
        for (int jn = 0; jn < 8; jn++) {
            o[jn][0] *= alpha0; o[jn][1] *= alpha0;
            o[jn][2] *= alpha1; o[jn][3] *= alpha1;
        }

        // ---- stage P (warp-private strip) ----
#pragma unroll
        for (int jn = 0; jn < 8; jn++) {
            uint32_t* p0 = &sP[prow0 * LDP + 8 * jn + 2 * c4];
            p0[0] = f2tf32(s[jn][0]);
            p0[1] = f2tf32(s[jn][1]);
            uint32_t* p1 = &sP[(prow0 + 8) * LDP + 8 * jn + 2 * c4];
            p1[0] = f2tf32(s[jn][2]);
            p1[1] = f2tf32(s[jn][3]);
        }
        __syncwarp();

        // ---- O += P V ----
#pragma unroll
        for (int kk = 0; kk < 8; kk++) {
            uint32_t ap[4];
            ap[0] = sP[prow0 * LDP + kk * 8 + c4];
            ap[1] = sP[(prow0 + 8) * LDP + kk * 8 + c4];
            ap[2] = sP[prow0 * LDP + kk * 8 + c4 + 4];
            ap[3] = sP[(prow0 + 8) * LDP + kk * 8 + c4 + 4];
#pragma unroll
            for (int jn = 0; jn < 8; jn++) {
                uint32_t b0 = sV[(8 * jn + r8) * LDV + kk * 8 + c4];
                uint32_t b1 = sV[(8 * jn + r8) * LDV + kk * 8 + c4 + 4];
                mma_tf32_16n8k8(o[jn], ap, b0, b1);
            }
        }
        __syncwarp();   // P strip reuse next iteration
    }

    // ---- epilogue: normalize + write ctx [B,S,D] ----
    float inv0 = 1.0f / l0, inv1 = 1.0f / l1;
    size_t row0 = ((size_t)b * S_ + qr0) * D_ + h * DK_;
    size_t row1 = ((size_t)b * S_ + qr1) * D_ + h * DK_;
#pragma unroll
    for (int jn = 0; jn < 8; jn++) {
        int col = 8 * jn + 2 * c4;
        *(float2*)&g_ctx[row0 + col] = make_float2(o[jn][0] * inv0, o[jn][1] * inv0);
        *(float2*)&g_ctx[row1 + col] = make_float2(o[jn][2] * inv1, o[jn][3] * inv1);
    }
}

// ---------------------------------------------------------------------------
// Launch
// ---------------------------------------------------------------------------
extern "C" void kernel_launch(void* const* d_in, const int* in_sizes, int n_in,
                              void* d_out, int out_size)
{
    const float* Q  = (const float*)d_in[0];
    const float* K  = (const float*)d_in[1];
    const float* V  = (const float*)d_in[2];
    const float* Wq = (const float*)d_in[3];
    const float* bq = (const float*)d_in[4];
    const float* Wk = (const float*)d_in[5];
    const float* bk = (const float*)d_in[6];
    const float* Wv = (const float*)d_in[7];
    const float* bv = (const float*)d_in[8];
    const float* Wo = (const float*)d_in[9];
    const float* bo = (const float*)d_in[10];
    float* out = (float*)d_out;

    cudaFuncSetAttribute(flash_tf32,
                         cudaFuncAttributeMaxDynamicSharedMemorySize, FSMEM);

    dim3 ggrid(D_ / 128, M_ / 128);   // (8, 64)
    gemm_tf32<<<ggrid, 256>>>(Q, Wq, bq, nullptr, 0);
    gemm_tf32<<<ggrid, 256>>>(K, Wk, bk, nullptr, 1);
    gemm_tf32<<<ggrid, 256>>>(V, Wv, bv, nullptr, 2);

    flash_tf32<<<dim3(S_ / 128, H_, B_), 256, FSMEM>>>();

    gemm_tf32<<<ggrid, 256>>>(nullptr, Wo, bo, out, 3);  // input = g_ctx
}

// round 6
// speedup vs baseline: 3.2382x; 1.0827x over previous
#include <cuda_runtime.h>
#include <cstdint>
#include <math.h>

// Problem constants
constexpr int B_  = 4;
constexpr int S_  = 2048;
constexpr int D_  = 1024;
constexpr int H_  = 16;
constexpr int DK_ = 64;
constexpr int M_  = B_ * S_;   // 8192

// Scratch (device globals — no allocation allowed)
__device__ float g_q[(size_t)B_ * H_ * S_ * DK_];   // [B,H,S,DK]
__device__ float g_k[(size_t)B_ * H_ * S_ * DK_];
__device__ float g_v[(size_t)B_ * H_ * S_ * DK_];
__device__ float g_ctx[(size_t)B_ * S_ * D_];       // [B,S,D]

// ---------------------------------------------------------------------------
// tf32 helpers (non-suffixed PTX: works under generic sm_103 target)
// ---------------------------------------------------------------------------
__device__ __forceinline__ uint32_t f2tf32(float f) {
    uint32_t r;
    asm("cvt.rna.tf32.f32 %0, %1;" : "=r"(r) : "f"(f));
    return r;
}

__device__ __forceinline__ void mma_tf32_16n8k8(float* c, const uint32_t* a,
                                                uint32_t b0, uint32_t b1) {
    asm volatile(
        "mma.sync.aligned.m16n8k8.row.col.f32.tf32.tf32.f32 "
        "{%0,%1,%2,%3}, {%4,%5,%6,%7}, {%8,%9}, {%0,%1,%2,%3};"
        : "+f"(c[0]), "+f"(c[1]), "+f"(c[2]), "+f"(c[3])
        : "r"(a[0]), "r"(a[1]), "r"(a[2]), "r"(a[3]), "r"(b0), "r"(b1));
}

// ---------------------------------------------------------------------------
// TF32 tensor-core GEMM: Y[M,N] = X @ W^T + bias  (unchanged from R4/R5, proven)
// ---------------------------------------------------------------------------
constexpr int BK  = 16;
constexpr int LDA = 20;

__global__ __launch_bounds__(256, 2) void gemm_tf32(
    const float* __restrict__ X, const float* __restrict__ W,
    const float* __restrict__ bias, float* __restrict__ dst, int which)
{
    __shared__ uint32_t As[2][128 * LDA];
    __shared__ uint32_t Bs[2][128 * LDA];

    const int tid = threadIdx.x;
    const int wid = tid >> 5;
    const int lane = tid & 31;
    const int m0 = blockIdx.y * 128;
    const int n0 = blockIdx.x * 128;
    const int warp_m = (wid & 3) * 32;
    const int warp_n = (wid >> 2) * 64;

    const float* Xin = (which == 3) ? (const float*)g_ctx : X;

    const int r0 = tid >> 2;
    const int kq = (tid & 3) * 4;

    const float* gA = Xin + (size_t)m0 * D_;
    const float* gB = W + (size_t)n0 * D_;

    float acc[2][8][4];
#pragma unroll
    for (int i = 0; i < 2; i++)
#pragma unroll
        for (int j = 0; j < 8; j++)
#pragma unroll
            for (int r = 0; r < 4; r++) acc[i][j][r] = 0.f;

    float4 pa0, pa1, pb0, pb1;

    auto ldg = [&](int t) {
        const float* a = gA + (size_t)r0 * D_ + t * BK + kq;
        pa0 = *(const float4*)a;
        pa1 = *(const float4*)(a + (size_t)64 * D_);
        const float* b = gB + (size_t)r0 * D_ + t * BK + kq;
        pb0 = *(const float4*)b;
        pb1 = *(const float4*)(b + (size_t)64 * D_);
    };
    auto sts = [&](int s) {
        uint32_t* A = As[s];
        uint32_t* Bsh = Bs[s];
        int o0 = r0 * LDA + kq;
        int o1 = (r0 + 64) * LDA + kq;
        A[o0 + 0] = f2tf32(pa0.x); A[o0 + 1] = f2tf32(pa0.y);
        A[o0 + 2] = f2tf32(pa0.z); A[o0 + 3] = f2tf32(pa0.w);
        A[o1 + 0] = f2tf32(pa1.x); A[o1 + 1] = f2tf32(pa1.y);
        A[o1 + 2] = f2tf32(pa1.z); A[o1 + 3] = f2tf32(pa1.w);
        Bsh[o0 + 0] = f2tf32(pb0.x); Bsh[o0 + 1] = f2tf32(pb0.y);
        Bsh[o0 + 2] = f2tf32(pb0.z); Bsh[o0 + 3] = f2tf32(pb0.w);
        Bsh[o1 + 0] = f2tf32(pb1.x); Bsh[o1 + 1] = f2tf32(pb1.y);
        Bsh[o1 + 2] = f2tf32(pb1.z); Bsh[o1 + 3] = f2tf32(pb1.w);
    };

    ldg(0);
    sts(0);
    __syncthreads();

    const int r8 = lane >> 2;
    const int c4 = lane & 3;

    for (int t = 0; t < D_ / BK; t++) {
        int s = t & 1;
        if (t < D_ / BK - 1) ldg(t + 1);

#pragma unroll
        for (int ks = 0; ks < 2; ks++) {
            const int kk = ks * 8;
            uint32_t a[2][4], b[8][2];
#pragma unroll
            for (int im = 0; im < 2; im++) {
                int mr = warp_m + 16 * im + r8;
                a[im][0] = As[s][mr * LDA + kk + c4];
                a[im][1] = As[s][(mr + 8) * LDA + kk + c4];
                a[im][2] = As[s][mr * LDA + kk + c4 + 4];
                a[im][3] = As[s][(mr + 8) * LDA + kk + c4 + 4];
            }
#pragma unroll
            for (int jn = 0; jn < 8; jn++) {
                int nr = warp_n + 8 * jn + r8;
                b[jn][0] = Bs[s][nr * LDA + kk + c4];
                b[jn][1] = Bs[s][nr * LDA + kk + c4 + 4];
            }
#pragma unroll
            for (int im = 0; im < 2; im++)
#pragma unroll
                for (int jn = 0; jn < 8; jn++)
                    mma_tf32_16n8k8(acc[im][jn], a[im], b[jn][0], b[jn][1]);
        }

        if (t < D_ / BK - 1) sts(s ^ 1);
        __syncthreads();
    }

    float* sh_out = (which == 0) ? g_q : (which == 1) ? g_k
                  : (which == 2) ? g_v : dst;
    const int c2 = (lane & 3) * 2;
#pragma unroll
    for (int im = 0; im < 2; im++) {
#pragma unroll
        for (int jn = 0; jn < 8; jn++) {
            int n = n0 + warp_n + 8 * jn + c2;
            float bx = bias[n], by = bias[n + 1];
            int mA = m0 + warp_m + 16 * im + r8;
            int mB = mA + 8;
            float2 v0 = make_float2(acc[im][jn][0] + bx, acc[im][jn][1] + by);
            float2 v1 = make_float2(acc[im][jn][2] + bx, acc[im][jn][3] + by);
            if (which < 3) {
                int h = n >> 6, dk = n & 63;
                int bA = mA >> 11, sA = mA & (S_ - 1);
                int bB = mB >> 11, sB = mB & (S_ - 1);
                *(float2*)&sh_out[(((size_t)(bA * H_ + h) * S_ + sA) << 6) + dk] = v0;
                *(float2*)&sh_out[(((size_t)(bB * H_ + h) * S_ + sB) << 6) + dk] = v1;
            } else {
                *(float2*)&sh_out[(size_t)mA * D_ + n] = v0;
                *(float2*)&sh_out[(size_t)mB * D_ + n] = v1;
            }
        }
    }
}

// ---------------------------------------------------------------------------
// Flash attention v2 (tf32 mma.sync).
// BQ=256 q rows / CTA, KV chunks of 64, 8 warps; warp w owns 32 q rows
// (two m16 tiles). K/V/P B/A-fragments shared across both tiles -> ~45%
// less smem traffic than v1. V stored ROW-MAJOR stride 72 (bank-bijective
// for the PV B-fragment pattern, packed STS.128 fill). K stride 68, P 68.
// ---------------------------------------------------------------------------
constexpr int LDK2 = 68;   // 68 % 32 == 4 -> 4*r8 + c4 bijective
constexpr int LDV2 = 72;   // 72 % 32 == 8 -> 8*c4 + r8 bijective
constexpr int LDP2 = 68;
constexpr int FSMEM = (64 * LDK2 + 64 * LDV2 + 256 * LDP2) * 4;  // 105472 B

__global__ __launch_bounds__(256, 1) void flash_tf32()
{
    extern __shared__ uint32_t sm[];
    uint32_t* sK = sm;
    uint32_t* sV = sm + 64 * LDK2;
    uint32_t* sP = sm + 64 * LDK2 + 64 * LDV2;

    const int tid = threadIdx.x;
    const int wid = tid >> 5;
    const int lane = tid & 31;
    const int r8 = lane >> 2;
    const int c4 = lane & 3;

    const int q0 = blockIdx.x * 256;
    const int h = blockIdx.y;
    const int b = blockIdx.z;
    const size_t base = (size_t)(b * H_ + h) * S_ * DK_;
    const float* qg = g_q + base;
    const float* kg = g_k + base;
    const float* vg = g_v + base;

    // Warp's q rows: two m16 tiles at wid*32 and wid*32+16.
    const int wr = wid * 32;

    // Q A-fragments (pre-scaled), loaded once; reused across all 32 chunks.
    uint32_t aq[2][8][4];
#pragma unroll
    for (int t = 0; t < 2; t++) {
        int row0 = q0 + wr + 16 * t + r8;
        int row1 = row0 + 8;
#pragma unroll
        for (int kk = 0; kk < 8; kk++) {
            int d0 = kk * 8 + c4;
            aq[t][kk][0] = f2tf32(qg[(size_t)row0 * DK_ + d0] * 0.125f);
            aq[t][kk][1] = f2tf32(qg[(size_t)row1 * DK_ + d0] * 0.125f);
            aq[t][kk][2] = f2tf32(qg[(size_t)row0 * DK_ + d0 + 4] * 0.125f);
            aq[t][kk][3] = f2tf32(qg[(size_t)row1 * DK_ + d0 + 4] * 0.125f);
        }
    }

    float mrow[2][2], lrow[2][2];
    float o0[8][4], o1[8][4];
#pragma unroll
    for (int t = 0; t < 2; t++) {
        mrow[t][0] = mrow[t][1] = -1e30f;
        lrow[t][0] = lrow[t][1] = 0.f;
    }
#pragma unroll
    for (int j = 0; j < 8; j++)
#pragma unroll
        for (int r = 0; r < 4; r++) { o0[j][r] = 0.f; o1[j][r] = 0.f; }

    const int prow0 = wr + r8;        // tile0 A rows: prow0, prow0+8
    const int prow1 = wr + 16 + r8;   // tile1

    for (int kb = 0; kb < S_; kb += 64) {
        __syncthreads();   // previous chunk fully consumed sK/sV
        // Fill: row-major, packed uint4 stores (conflict-free).
#pragma unroll
        for (int i = 0; i < 4; i++) {
            int idx = tid + i * 256;          // 0..1023
            int row = idx >> 4;               // key 0..63
            int cc = (idx & 15) * 4;          // dk
            float4 kv4 = *(const float4*)&kg[(size_t)(kb + row) * DK_ + cc];
            uint4 kp = make_uint4(f2tf32(kv4.x), f2tf32(kv4.y),
                                  f2tf32(kv4.z), f2tf32(kv4.w));
            *(uint4*)&sK[row * LDK2 + cc] = kp;
            float4 vv4 = *(const float4*)&vg[(size_t)(kb + row) * DK_ + cc];
            uint4 vp = make_uint4(f2tf32(vv4.x), f2tf32(vv4.y),
                                  f2tf32(vv4.z), f2tf32(vv4.w));
            *(uint4*)&sV[row * LDV2 + cc] = vp;
        }
        __syncthreads();

        // ---- S = Q K^T, both m-tiles sharing every K fragment ----
        float s0[8][4], s1[8][4];
#pragma unroll
        for (int j = 0; j < 8; j++)
#pragma unroll
            for (int r = 0; r < 4; r++) { s0[j][r] = 0.f; s1[j][r] = 0.f; }

#pragma unroll
        for (int kk = 0; kk < 8; kk++) {
#pragma unroll
            for (int jn = 0; jn < 8; jn++) {
                uint32_t b0 = sK[(8 * jn + r8) * LDK2 + kk * 8 + c4];
                uint32_t b1 = sK[(8 * jn + r8) * LDK2 + kk * 8 + c4 + 4];
                mma_tf32_16n8k8(s0[jn], aq[0][kk], b0, b1);
                mma_tf32_16n8k8(s1[jn], aq[1][kk], b0, b1);
            }
        }

        // ---- online softmax + stage P, per tile ----
#pragma unroll
        for (int t = 0; t < 2; t++) {
            float (*s)[4] = (t == 0) ? s0 : s1;
            float (*o)[4] = (t == 0) ? o0 : o1;
            float mx0 = -1e30f, mx1 = -1e30f;
#pragma unroll
            for (int jn = 0; jn < 8; jn++) {
                mx0 = fmaxf(mx0, fmaxf(s[jn][0], s[jn][1]));
                mx1 = fmaxf(mx1, fmaxf(s[jn][2], s[jn][3]));
            }
            mx0 = fmaxf(mx0, __shfl_xor_sync(0xffffffffu, mx0, 1));
            mx0 = fmaxf(mx0, __shfl_xor_sync(0xffffffffu, mx0, 2));
            mx1 = fmaxf(mx1, __shfl_xor_sync(0xffffffffu, mx1, 1));
            mx1 = fmaxf(mx1, __shfl_xor_sync(0xffffffffu, mx1, 2));
            float mn0 = fmaxf(mrow[t][0], mx0), mn1 = fmaxf(mrow[t][1], mx1);
            float alpha0 = __expf(mrow[t][0] - mn0);
            float alpha1 = __expf(mrow[t][1] - mn1);
            float sum0 = 0.f, sum1 = 0.f;
#pragma unroll
            for (int jn = 0; jn < 8; jn++) {
                s[jn][0] = __expf(s[jn][0] - mn0);
                s[jn][1] = __expf(s[jn][1] - mn0);
                s[jn][2] = __expf(s[jn][2] - mn1);
                s[jn][3] = __expf(s[jn][3] - mn1);
                sum0 += s[jn][0] + s[jn][1];
                sum1 += s[jn][2] + s[jn][3];
            }
            sum0 += __shfl_xor_sync(0xffffffffu, sum0, 1);
            sum0 += __shfl_xor_sync(0xffffffffu, sum0, 2);
            sum1 += __shfl_xor_sync(0xffffffffu, sum1, 1);
            sum1 += __shfl_xor_sync(0xffffffffu, sum1, 2);
            lrow[t][0] = lrow[t][0] * alpha0 + sum0;
            lrow[t][1] = lrow[t][1] * alpha1 + sum1;
            mrow[t][0] = mn0;
            mrow[t][1] = mn1;
#pragma unroll
            for (int jn = 0; jn < 8; jn++) {
                o[jn][0] *= alpha0; o[jn][1] *= alpha0;
                o[jn][2] *= alpha1; o[jn][3] *= alpha1;
            }
            int pr = (t == 0) ? prow0 : prow1;
#pragma unroll
            for (int jn = 0; jn < 8; jn++) {
                uint32_t* p0 = &sP[pr * LDP2 + 8 * jn + 2 * c4];
                p0[0] = f2tf32(s[jn][0]);
                p0[1] = f2tf32(s[jn][1]);
                uint32_t* p1 = &sP[(pr + 8) * LDP2 + 8 * jn + 2 * c4];
                p1[0] = f2tf32(s[jn][2]);
                p1[1] = f2tf32(s[jn][3]);
            }
        }
        __syncwarp();

        // ---- O += P V, both tiles sharing every V fragment ----
#pragma unroll
        for (int kk = 0; kk < 8; kk++) {
            uint32_t ap0[4], ap1[4];
            ap0[0] = sP[prow0 * LDP2 + kk * 8 + c4];
            ap0[1] = sP[(prow0 + 8) * LDP2 + kk * 8 + c4];
            ap0[2] = sP[prow0 * LDP2 + kk * 8 + c4 + 4];
            ap0[3] = sP[(prow0 + 8) * LDP2 + kk * 8 + c4 + 4];
            ap1[0] = sP[prow1 * LDP2 + kk * 8 + c4];
            ap1[1] = sP[(prow1 + 8) * LDP2 + kk * 8 + c4];
            ap1[2] = sP[prow1 * LDP2 + kk * 8 + c4 + 4];
            ap1[3] = sP[(prow1 + 8) * LDP2 + kk * 8 + c4 + 4];
#pragma unroll
            for (int jn = 0; jn < 8; jn++) {
                uint32_t b0 = sV[(kk * 8 + c4) * LDV2 + 8 * jn + r8];
                uint32_t b1 = sV[(kk * 8 + c4 + 4) * LDV2 + 8 * jn + r8];
                mma_tf32_16n8k8(o0[jn], ap0, b0, b1);
                mma_tf32_16n8k8(o1[jn], ap1, b0, b1);
            }
        }
        __syncwarp();   // P strip reused next iteration
    }

    // ---- epilogue: normalize + write ctx [B,S,D] ----
#pragma unroll
    for (int t = 0; t < 2; t++) {
        float (*o)[4] = (t == 0) ? o0 : o1;
        float inv0 = 1.0f / lrow[t][0], inv1 = 1.0f / lrow[t][1];
        int row0 = q0 + wr + 16 * t + r8;
        int row1 = row0 + 8;
        size_t g0 = ((size_t)b * S_ + row0) * D_ + h * DK_;
        size_t g1 = ((size_t)b * S_ + row1) * D_ + h * DK_;
#pragma unroll
        for (int jn = 0; jn < 8; jn++) {
            int col = 8 * jn + 2 * c4;
            *(float2*)&g_ctx[g0 + col] = make_float2(o[jn][0] * inv0, o[jn][1] * inv0);
            *(float2*)&g_ctx[g1 + col] = make_float2(o[jn][2] * inv1, o[jn][3] * inv1);
        }
    }
}

// ---------------------------------------------------------------------------
// Launch
// ---------------------------------------------------------------------------
extern "C" void kernel_launch(void* const* d_in, const int* in_sizes, int n_in,
                              void* d_out, int out_size)
{
    const float* Q  = (const float*)d_in[0];
    const float* K  = (const float*)d_in[1];
    const float* V  = (const float*)d_in[2];
    const float* Wq = (const float*)d_in[3];
    const float* bq = (const float*)d_in[4];
    const float* Wk = (const float*)d_in[5];
    const float* bk = (const float*)d_in[6];
    const float* Wv = (const float*)d_in[7];
    const float* bv = (const float*)d_in[8];
    const float* Wo = (const float*)d_in[9];
    const float* bo = (const float*)d_in[10];
    float* out = (float*)d_out;

    cudaFuncSetAttribute(flash_tf32,
                         cudaFuncAttributeMaxDynamicSharedMemorySize, FSMEM);

    dim3 ggrid(D_ / 128, M_ / 128);   // (8, 64)
    gemm_tf32<<<ggrid, 256>>>(Q, Wq, bq, nullptr, 0);
    gemm_tf32<<<ggrid, 256>>>(K, Wk, bk, nullptr, 1);
    gemm_tf32<<<ggrid, 256>>>(V, Wv, bv, nullptr, 2);

    flash_tf32<<<dim3(S_ / 256, H_, B_), 256, FSMEM>>>();

    gemm_tf32<<<ggrid, 256>>>(nullptr, Wo, bo, out, 3);  // input = g_ctx
}

// round 7
// speedup vs baseline: 3.3461x; 1.0333x over previous
#include <cuda_runtime.h>
#include <cstdint>
#include <math.h>

// Problem constants
constexpr int B_  = 4;
constexpr int S_  = 2048;
constexpr int D_  = 1024;
constexpr int H_  = 16;
constexpr int DK_ = 64;
constexpr int M_  = B_ * S_;   // 8192

// Scratch (device globals — no allocation allowed)
__device__ float g_q[(size_t)B_ * H_ * S_ * DK_];   // [B,H,S,DK]
__device__ float g_k[(size_t)B_ * H_ * S_ * DK_];
__device__ float g_v[(size_t)B_ * H_ * S_ * DK_];
__device__ float g_ctx[(size_t)B_ * S_ * D_];       // [B,S,D]

// ---------------------------------------------------------------------------
// tf32 / async helpers (non-suffixed PTX: works under generic sm_103 target)
// ---------------------------------------------------------------------------
__device__ __forceinline__ uint32_t f2tf32(float f) {
    uint32_t r;
    asm("cvt.rna.tf32.f32 %0, %1;" : "=r"(r) : "f"(f));
    return r;
}

__device__ __forceinline__ void mma_tf32_16n8k8(float* c, const uint32_t* a,
                                                uint32_t b0, uint32_t b1) {
    asm volatile(
        "mma.sync.aligned.m16n8k8.row.col.f32.tf32.tf32.f32 "
        "{%0,%1,%2,%3}, {%4,%5,%6,%7}, {%8,%9}, {%0,%1,%2,%3};"
        : "+f"(c[0]), "+f"(c[1]), "+f"(c[2]), "+f"(c[3])
        : "r"(a[0]), "r"(a[1]), "r"(a[2]), "r"(a[3]), "r"(b0), "r"(b1));
}

__device__ __forceinline__ uint32_t smem_u32(const void* p) {
    uint32_t a;
    asm("{ .reg .u64 t; cvta.to.shared.u64 t, %1; cvt.u32.u64 %0, t; }"
        : "=r"(a) : "l"(p));
    return a;
}
__device__ __forceinline__ void cp_async16(uint32_t saddr, const void* g) {
    asm volatile("cp.async.ca.shared.global [%0], [%1], 16;"
                 :: "r"(saddr), "l"(g));
}
#define CP_COMMIT() asm volatile("cp.async.commit_group;" ::: "memory")
#define CP_WAIT0()  asm volatile("cp.async.wait_group 0;" ::: "memory")

// ---------------------------------------------------------------------------
// TF32 tensor-core GEMM: Y[M,N] = X @ W^T + bias  (unchanged, proven)
// ---------------------------------------------------------------------------
constexpr int BK  = 16;
constexpr int LDA = 20;

__global__ __launch_bounds__(256, 2) void gemm_tf32(
    const float* __restrict__ X, const float* __restrict__ W,
    const float* __restrict__ bias, float* __restrict__ dst, int which)
{
    __shared__ uint32_t As[2][128 * LDA];
    __shared__ uint32_t Bs[2][128 * LDA];

    const int tid = threadIdx.x;
    const int wid = tid >> 5;
    const int lane = tid & 31;
    const int m0 = blockIdx.y * 128;
    const int n0 = blockIdx.x * 128;
    const int warp_m = (wid & 3) * 32;
    const int warp_n = (wid >> 2) * 64;

    const float* Xin = (which == 3) ? (const float*)g_ctx : X;

    const int r0 = tid >> 2;
    const int kq = (tid & 3) * 4;

    const float* gA = Xin + (size_t)m0 * D_;
    const float* gB = W + (size_t)n0 * D_;

    float acc[2][8][4];
#pragma unroll
    for (int i = 0; i < 2; i++)
#pragma unroll
        for (int j = 0; j < 8; j++)
#pragma unroll
            for (int r = 0; r < 4; r++) acc[i][j][r] = 0.f;

    float4 pa0, pa1, pb0, pb1;

    auto ldg = [&](int t) {
        const float* a = gA + (size_t)r0 * D_ + t * BK + kq;
        pa0 = *(const float4*)a;
        pa1 = *(const float4*)(a + (size_t)64 * D_);
        const float* b = gB + (size_t)r0 * D_ + t * BK + kq;
        pb0 = *(const float4*)b;
        pb1 = *(const float4*)(b + (size_t)64 * D_);
    };
    auto sts = [&](int s) {
        uint32_t* A = As[s];
        uint32_t* Bsh = Bs[s];
        int o0 = r0 * LDA + kq;
        int o1 = (r0 + 64) * LDA + kq;
        A[o0 + 0] = f2tf32(pa0.x); A[o0 + 1] = f2tf32(pa0.y);
        A[o0 + 2] = f2tf32(pa0.z); A[o0 + 3] = f2tf32(pa0.w);
        A[o1 + 0] = f2tf32(pa1.x); A[o1 + 1] = f2tf32(pa1.y);
        A[o1 + 2] = f2tf32(pa1.z); A[o1 + 3] = f2tf32(pa1.w);
        Bsh[o0 + 0] = f2tf32(pb0.x); Bsh[o0 + 1] = f2tf32(pb0.y);
        Bsh[o0 + 2] = f2tf32(pb0.z); Bsh[o0 + 3] = f2tf32(pb0.w);
        Bsh[o1 + 0] = f2tf32(pb1.x); Bsh[o1 + 1] = f2tf32(pb1.y);
        Bsh[o1 + 2] = f2tf32(pb1.z); Bsh[o1 + 3] = f2tf32(pb1.w);
    };

    ldg(0);
    sts(0);
    __syncthreads();

    const int r8 = lane >> 2;
    const int c4 = lane & 3;

    for (int t = 0; t < D_ / BK; t++) {
        int s = t & 1;
        if (t < D_ / BK - 1) ldg(t + 1);

#pragma unroll
        for (int ks = 0; ks < 2; ks++) {
            const int kk = ks * 8;
            uint32_t a[2][4], b[8][2];
#pragma unroll
            for (int im = 0; im < 2; im++) {
                int mr = warp_m + 16 * im + r8;
                a[im][0] = As[s][mr * LDA + kk + c4];
                a[im][1] = As[s][(mr + 8) * LDA + kk + c4];
                a[im][2] = As[s][mr * LDA + kk + c4 + 4];
                a[im][3] = As[s][(mr + 8) * LDA + kk + c4 + 4];
            }
#pragma unroll
            for (int jn = 0; jn < 8; jn++) {
                int nr = warp_n + 8 * jn + r8;
                b[jn][0] = Bs[s][nr * LDA + kk + c4];
                b[jn][1] = Bs[s][nr * LDA + kk + c4 + 4];
            }
#pragma unroll
            for (int im = 0; im < 2; im++)
#pragma unroll
                for (int jn = 0; jn < 8; jn++)
                    mma_tf32_16n8k8(acc[im][jn], a[im], b[jn][0], b[jn][1]);
        }

        if (t < D_ / BK - 1) sts(s ^ 1);
        __syncthreads();
    }

    float* sh_out = (which == 0) ? g_q : (which == 1) ? g_k
                  : (which == 2) ? g_v : dst;
    const int c2 = (lane & 3) * 2;
#pragma unroll
    for (int im = 0; im < 2; im++) {
#pragma unroll
        for (int jn = 0; jn < 8; jn++) {
            int n = n0 + warp_n + 8 * jn + c2;
            float bx = bias[n], by = bias[n + 1];
            int mA = m0 + warp_m + 16 * im + r8;
            int mB = mA + 8;
            float2 v0 = make_float2(acc[im][jn][0] + bx, acc[im][jn][1] + by);
            float2 v1 = make_float2(acc[im][jn][2] + bx, acc[im][jn][3] + by);
            if (which < 3) {
                int h = n >> 6, dk = n & 63;
                int bA = mA >> 11, sA = mA & (S_ - 1);
                int bB = mB >> 11, sB = mB & (S_ - 1);
                *(float2*)&sh_out[(((size_t)(bA * H_ + h) * S_ + sA) << 6) + dk] = v0;
                *(float2*)&sh_out[(((size_t)(bB * H_ + h) * S_ + sB) << 6) + dk] = v1;
            } else {
                *(float2*)&sh_out[(size_t)mA * D_ + n] = v0;
                *(float2*)&sh_out[(size_t)mB * D_ + n] = v1;
            }
        }
    }
}

// ---------------------------------------------------------------------------
// Flash attention v3 (tf32 mma.sync + cp.async double-buffered K/V).
// BQ=256 q rows / CTA, KV chunks of 64, 8 warps, 2 m-tiles per warp.
// K/V land in smem as RAW fp32 via cp.async (2 stages, chunk c+1 load
// overlaps chunk c compute); tf32 conversion happens at fragment load.
// ---------------------------------------------------------------------------
constexpr int LDK2 = 68;   // 68 % 32 == 4 -> 4*r8 + c4 bijective
constexpr int LDV2 = 72;   // 72 % 32 == 8 -> 8*c4 + r8 bijective
constexpr int LDP2 = 68;
constexpr int FSMEM = (2 * 64 * LDK2 + 2 * 64 * LDV2 + 256 * LDP2) * 4; // 141312

__global__ __launch_bounds__(256, 1) void flash_tf32()
{
    extern __shared__ float smf[];
    float* sKf = smf;                        // 2 stages of [64][LDK2]
    float* sVf = smf + 2 * 64 * LDK2;        // 2 stages of [64][LDV2]
    uint32_t* sP = (uint32_t*)(smf + 2 * 64 * LDK2 + 2 * 64 * LDV2);

    const uint32_t skb = smem_u32(sKf);
    const uint32_t svb = smem_u32(sVf);

    const int tid = threadIdx.x;
    const int wid = tid >> 5;
    const int lane = tid & 31;
    const int r8 = lane >> 2;
    const int c4 = lane & 3;

    const int q0 = blockIdx.x * 256;
    const int h = blockIdx.y;
    const int b = blockIdx.z;
    const size_t base = (size_t)(b * H_ + h) * S_ * DK_;
    const float* qg = g_q + base;
    const float* kg = g_k + base;
    const float* vg = g_v + base;

    const int wr = wid * 32;

    // Q A-fragments (pre-scaled), loaded once; reused across all 32 chunks.
    uint32_t aq[2][8][4];
#pragma unroll
    for (int t = 0; t < 2; t++) {
        int row0 = q0 + wr + 16 * t + r8;
        int row1 = row0 + 8;
#pragma unroll
        for (int kk = 0; kk < 8; kk++) {
            int d0 = kk * 8 + c4;
            aq[t][kk][0] = f2tf32(qg[(size_t)row0 * DK_ + d0] * 0.125f);
            aq[t][kk][1] = f2tf32(qg[(size_t)row1 * DK_ + d0] * 0.125f);
            aq[t][kk][2] = f2tf32(qg[(size_t)row0 * DK_ + d0 + 4] * 0.125f);
            aq[t][kk][3] = f2tf32(qg[(size_t)row1 * DK_ + d0 + 4] * 0.125f);
        }
    }

    float mrow[2][2], lrow[2][2];
    float o0[8][4], o1[8][4];
#pragma unroll
    for (int t = 0; t < 2; t++) {
        mrow[t][0] = mrow[t][1] = -1e30f;
        lrow[t][0] = lrow[t][1] = 0.f;
    }
#pragma unroll
    for (int j = 0; j < 8; j++)
#pragma unroll
        for (int r = 0; r < 4; r++) { o0[j][r] = 0.f; o1[j][r] = 0.f; }

    const int prow0 = wr + r8;
    const int prow1 = wr + 16 + r8;

    // Per-thread fill coordinates (4 x 16B per tensor per chunk).
    const int frow0 = tid >> 4;          // 0..15
    const int fcc = (tid & 15) * 4;      // 0..60

    auto issue_chunk = [&](int kb, int st) {
#pragma unroll
        for (int i = 0; i < 4; i++) {
            int row = frow0 + i * 16;
            const float* kp = &kg[(size_t)(kb + row) * DK_ + fcc];
            const float* vp = &vg[(size_t)(kb + row) * DK_ + fcc];
            cp_async16(skb + (uint32_t)(st * 64 * LDK2 + row * LDK2 + fcc) * 4, kp);
            cp_async16(svb + (uint32_t)(st * 64 * LDV2 + row * LDV2 + fcc) * 4, vp);
        }
        CP_COMMIT();
    };

    issue_chunk(0, 0);

    for (int c = 0; c < S_ / 64; c++) {
        const int st = c & 1;
        CP_WAIT0();
        __syncthreads();
        if (c + 1 < S_ / 64) issue_chunk((c + 1) * 64, st ^ 1);

        const float* sKc = sKf + st * 64 * LDK2;
        const float* sVc = sVf + st * 64 * LDV2;

        // ---- S = Q K^T, both m-tiles sharing every K fragment ----
        float s0[8][4], s1[8][4];
#pragma unroll
        for (int j = 0; j < 8; j++)
#pragma unroll
            for (int r = 0; r < 4; r++) { s0[j][r] = 0.f; s1[j][r] = 0.f; }

#pragma unroll
        for (int kk = 0; kk < 8; kk++) {
#pragma unroll
            for (int jn = 0; jn < 8; jn++) {
                const float* kr = &sKc[(8 * jn + r8) * LDK2 + kk * 8 + c4];
                uint32_t b0 = f2tf32(kr[0]);
                uint32_t b1 = f2tf32(kr[4]);
                mma_tf32_16n8k8(s0[jn], aq[0][kk], b0, b1);
                mma_tf32_16n8k8(s1[jn], aq[1][kk], b0, b1);
            }
        }

        // ---- online softmax + stage P, per tile ----
#pragma unroll
        for (int t = 0; t < 2; t++) {
            float (*s)[4] = (t == 0) ? s0 : s1;
            float (*o)[4] = (t == 0) ? o0 : o1;
            float mx0 = -1e30f, mx1 = -1e30f;
#pragma unroll
            for (int jn = 0; jn < 8; jn++) {
                mx0 = fmaxf(mx0, fmaxf(s[jn][0], s[jn][1]));
                mx1 = fmaxf(mx1, fmaxf(s[jn][2], s[jn][3]));
            }
            mx0 = fmaxf(mx0, __shfl_xor_sync(0xffffffffu, mx0, 1));
            mx0 = fmaxf(mx0, __shfl_xor_sync(0xffffffffu, mx0, 2));
            mx1 = fmaxf(mx1, __shfl_xor_sync(0xffffffffu, mx1, 1));
            mx1 = fmaxf(mx1, __shfl_xor_sync(0xffffffffu, mx1, 2));
            float mn0 = fmaxf(mrow[t][0], mx0), mn1 = fmaxf(mrow[t][1], mx1);
            float alpha0 = __expf(mrow[t][0] - mn0);
            float alpha1 = __expf(mrow[t][1] - mn1);
            float sum0 = 0.f, sum1 = 0.f;
#pragma unroll
            for (int jn = 0; jn < 8; jn++) {
                s[jn][0] = __expf(s[jn][0] - mn0);
                s[jn][1] = __expf(s[jn][1] - mn0);
                s[jn][2] = __expf(s[jn][2] - mn1);
                s[jn][3] = __expf(s[jn][3] - mn1);
                sum0 += s[jn][0] + s[jn][1];
                sum1 += s[jn][2] + s[jn][3];
            }
            sum0 += __shfl_xor_sync(0xffffffffu, sum0, 1);
            sum0 += __shfl_xor_sync(0xffffffffu, sum0, 2);
            sum1 += __shfl_xor_sync(0xffffffffu, sum1, 1);
            sum1 += __shfl_xor_sync(0xffffffffu, sum1, 2);
            lrow[t][0] = lrow[t][0] * alpha0 + sum0;
            lrow[t][1] = lrow[t][1] * alpha1 + sum1;
            mrow[t][0] = mn0;
            mrow[t][1] = mn1;
#pragma unroll
            for (int jn = 0; jn < 8; jn++) {
                o[jn][0] *= alpha0; o[jn][1] *= alpha0;
                o[jn][2] *= alpha1; o[jn][3] *= alpha1;
            }
            int pr = (t == 0) ? prow0 : prow1;
#pragma unroll
            for (int jn = 0; jn < 8; jn++) {
                uint32_t* p0 = &sP[pr * LDP2 + 8 * jn + 2 * c4];
                p0[0] = f2tf32(s[jn][0]);
                p0[1] = f2tf32(s[jn][1]);
                uint32_t* p1 = &sP[(pr + 8) * LDP2 + 8 * jn + 2 * c4];
                p1[0] = f2tf32(s[jn][2]);
                p1[1] = f2tf32(s[jn][3]);
            }
        }
        __syncwarp();

        // ---- O += P V, both tiles sharing every V fragment ----
#pragma unroll
        for (int kk = 0; kk < 8; kk++) {
            uint32_t ap0[4], ap1[4];
            ap0[0] = sP[prow0 * LDP2 + kk * 8 + c4];
            ap0[1] = sP[(prow0 + 8) * LDP2 + kk * 8 + c4];
            ap0[2] = sP[prow0 * LDP2 + kk * 8 + c4 + 4];
            ap0[3] = sP[(prow0 + 8) * LDP2 + kk * 8 + c4 + 4];
            ap1[0] = sP[prow1 * LDP2 + kk * 8 + c4];
            ap1[1] = sP[(prow1 + 8) * LDP2 + kk * 8 + c4];
            ap1[2] = sP[prow1 * LDP2 + kk * 8 + c4 + 4];
            ap1[3] = sP[(prow1 + 8) * LDP2 + kk * 8 + c4 + 4];
#pragma unroll
            for (int jn = 0; jn < 8; jn++) {
                uint32_t b0 = f2tf32(sVc[(kk * 8 + c4) * LDV2 + 8 * jn + r8]);
                uint32_t b1 = f2tf32(sVc[(kk * 8 + c4 + 4) * LDV2 + 8 * jn + r8]);
                mma_tf32_16n8k8(o0[jn], ap0, b0, b1);
                mma_tf32_16n8k8(o1[jn], ap1, b0, b1);
            }
        }
        __syncwarp();   // P strip reused next iteration
    }

    // ---- epilogue: normalize + write ctx [B,S,D] ----
#pragma unroll
    for (int t = 0; t < 2; t++) {
        float (*o)[4] = (t == 0) ? o0 : o1;
        float inv0 = 1.0f / lrow[t][0], inv1 = 1.0f / lrow[t][1];
        int row0 = q0 + wr + 16 * t + r8;
        int row1 = row0 + 8;
        size_t g0 = ((size_t)b * S_ + row0) * D_ + h * DK_;
        size_t g1 = ((size_t)b * S_ + row1) * D_ + h * DK_;
#pragma unroll
        for (int jn = 0; jn < 8; jn++) {
            int col = 8 * jn + 2 * c4;
            *(float2*)&g_ctx[g0 + col] = make_float2(o[jn][0] * inv0, o[jn][1] * inv0);
            *(float2*)&g_ctx[g1 + col] = make_float2(o[jn][2] * inv1, o[jn][3] * inv1);
        }
    }
}

// ---------------------------------------------------------------------------
// Launch
// ---------------------------------------------------------------------------
extern "C" void kernel_launch(void* const* d_in, const int* in_sizes, int n_in,
                              void* d_out, int out_size)
{
    const float* Q  = (const float*)d_in[0];
    const float* K  = (const float*)d_in[1];
    const float* V  = (const float*)d_in[2];
    const float* Wq = (const float*)d_in[3];
    const float* bq = (const float*)d_in[4];
    const float* Wk = (const float*)d_in[5];
    const float* bk = (const float*)d_in[6];
    const float* Wv = (const float*)d_in[7];
    const float* bv = (const float*)d_in[8];
    const float* Wo = (const float*)d_in[9];
    const float* bo = (const float*)d_in[10];
    float* out = (float*)d_out;

    cudaFuncSetAttribute(flash_tf32,
                         cudaFuncAttributeMaxDynamicSharedMemorySize, FSMEM);

    dim3 ggrid(D_ / 128, M_ / 128);   // (8, 64)
    gemm_tf32<<<ggrid, 256>>>(Q, Wq, bq, nullptr, 0);
    gemm_tf32<<<ggrid, 256>>>(K, Wk, bk, nullptr, 1);
    gemm_tf32<<<ggrid, 256>>>(V, Wv, bv, nullptr, 2);

    flash_tf32<<<dim3(S_ / 256, H_, B_), 256, FSMEM>>>();

    gemm_tf32<<<ggrid, 256>>>(nullptr, Wo, bo, out, 3);  // input = g_ctx
}